// round 15
// baseline (speedup 1.0000x reference)
#include <cuda_runtime.h>
#include <cuda_fp16.h>
#include <math_constants.h>
#include <cstdint>

// Problem constants
#define BB 2
#define SS 2048
#define DD 1024
#define HH 16
#define DK 64
#define FF 4096
#define MR (BB*SS)          // 4096 rows
#define QKVN 3072

// ---------------- scratch (static device globals: alloc-free rule) ----------
__device__ __half g_nX16  [MR*DD];
__device__ __half g_qkv16 [(size_t)MR*QKVN];
__device__ __half g_ctx16 [MR*DD];
__device__ __half g_h16   [(size_t)MR*FF];
__device__ float  g_X1    [MR*DD];
__device__ __half g_Wqkv16[(size_t)DD*QKVN];   // [K=1024, N=3072] interleaved
__device__ __half g_Wo16  [DD*DD];             // [K=1024, N=1024]
__device__ __half g_W1h   [(size_t)DD*FF];     // [K=1024, N=4096]
__device__ __half g_W2h   [(size_t)FF*DD];     // [K=4096, N=1024]

// ---------------- small helpers ---------------------------------------------
__device__ __forceinline__ uint32_t smem_u32(const void* p) {
    uint32_t a;
    asm("{ .reg .u64 t; cvta.to.shared.u64 t, %1; cvt.u32.u64 %0, t; }"
        : "=r"(a) : "l"(p));
    return a;
}
__device__ __forceinline__ void cp16(uint32_t s, const void* g) {
    asm volatile("cp.async.cg.shared.global [%0], [%1], 16;" :: "r"(s), "l"(g));
}
__device__ __forceinline__ void ldsm4(uint32_t* r, uint32_t addr) {
    asm volatile(
        "ldmatrix.sync.aligned.m8n8.x4.shared.b16 {%0,%1,%2,%3}, [%4];"
        : "=r"(r[0]), "=r"(r[1]), "=r"(r[2]), "=r"(r[3]) : "r"(addr));
}
__device__ __forceinline__ void ldsm4t(uint32_t* r, uint32_t addr) {
    asm volatile(
        "ldmatrix.sync.aligned.m8n8.x4.trans.shared.b16 {%0,%1,%2,%3}, [%4];"
        : "=r"(r[0]), "=r"(r[1]), "=r"(r[2]), "=r"(r[3]) : "r"(addr));
}
__device__ __forceinline__ void mma_f16(float* c, const uint32_t* a,
                                        uint32_t b0, uint32_t b1) {
    asm volatile(
        "mma.sync.aligned.m16n8k16.row.col.f32.f16.f16.f32 "
        "{%0,%1,%2,%3}, {%4,%5,%6,%7}, {%8,%9}, {%0,%1,%2,%3};"
        : "+f"(c[0]), "+f"(c[1]), "+f"(c[2]), "+f"(c[3])
        : "r"(a[0]), "r"(a[1]), "r"(a[2]), "r"(a[3]), "r"(b0), "r"(b1));
}
__device__ __forceinline__ uint32_t packh2(float x, float y) {
    __half2 h = __floats2half2_rn(x, y);
    return *(uint32_t*)&h;
}

// ---------------- single fused weight convert (fp32 -> fp16) -----------------
// Covers: Wq/Wk/Wv -> interleaved Wqkv16, plus flat Wo, W1, W2.
__global__ __launch_bounds__(256)
void convert_all_kernel(const float* __restrict__ wq, const float* __restrict__ wk,
                        const float* __restrict__ wv, const float* __restrict__ wo,
                        const float* __restrict__ w1, const float* __restrict__ w2,
                        __half* __restrict__ oqkv, __half* __restrict__ owo,
                        __half* __restrict__ ow1, __half* __restrict__ ow2)
{
    const int per = DD * DD / 4;                   // 262144 float4s per DDxDD
    const int nqkv = 3 * per;
    const int nw1  = DD * FF / 4;
    const int nw2  = FF * DD / 4;
    const int tot  = nqkv + per + nw1 + nw2;
    for (int idx = blockIdx.x * 256 + threadIdx.x; idx < tot;
         idx += gridDim.x * 256) {
        float4 val;
        __half2* o;
        if (idx < nqkv) {
            const int m   = idx / per;
            const int rem = idx - m * per;
            const int r   = rem >> 8;
            const int c4  = (rem & 255) << 2;
            const float* src = (m == 0 ? wq : m == 1 ? wk : wv)
                             + (size_t)r * DD + c4;
            val = *(const float4*)src;
            o = (__half2*)(oqkv + (size_t)r * QKVN + m * DD + c4);
        } else {
            int i = idx - nqkv;
            const float* src;
            __half* dst;
            if (i < per)              { src = wo; dst = owo; }
            else if ((i -= per) < nw1) { src = w1; dst = ow1; }
            else                       { i -= nw1; src = w2; dst = ow2; }
            val = *(const float4*)(src + (size_t)i * 4);
            o = (__half2*)(dst + (size_t)i * 4);
        }
        o[0] = __floats2half2_rn(val.x, val.y);
        o[1] = __floats2half2_rn(val.z, val.w);
    }
}

// ---------------- LayerNorm (fp32 in, fp16 out) ------------------------------
__global__ __launch_bounds__(256)
void ln_kernel(const float* __restrict__ X, const float* __restrict__ g,
               const float* __restrict__ b, __half* __restrict__ Y)
{
    const int row = blockIdx.x;
    const int tid = threadIdx.x;
    const float4 x = ((const float4*)(X + (size_t)row * DD))[tid];

    float s  = x.x + x.y + x.z + x.w;
    float ss = x.x*x.x + x.y*x.y + x.z*x.z + x.w*x.w;
    #pragma unroll
    for (int o = 16; o; o >>= 1) {
        s  += __shfl_xor_sync(0xffffffffu, s,  o);
        ss += __shfl_xor_sync(0xffffffffu, ss, o);
    }
    __shared__ float sw[8], sw2[8];
    const int w = tid >> 5, ln = tid & 31;
    if (ln == 0) { sw[w] = s; sw2[w] = ss; }
    __syncthreads();
    float tot = 0.f, tot2 = 0.f;
    #pragma unroll
    for (int i = 0; i < 8; i++) { tot += sw[i]; tot2 += sw2[i]; }

    const float mean = tot * (1.0f / DD);
    const float var  = tot2 * (1.0f / DD) - mean * mean;
    const float rstd = rsqrtf(var + 1e-5f);

    const float4 gv = ((const float4*)g)[tid];
    const float4 bv = ((const float4*)b)[tid];
    __half2 h01 = __floats2half2_rn((x.x - mean) * rstd * gv.x + bv.x,
                                    (x.y - mean) * rstd * gv.y + bv.y);
    __half2 h23 = __floats2half2_rn((x.z - mean) * rstd * gv.z + bv.z,
                                    (x.w - mean) * rstd * gv.w + bv.w);
    __half2* yp = (__half2*)(Y + (size_t)row * DD + tid * 4);
    yp[0] = h01; yp[1] = h23;
}

// ---------------- fp16 mma.sync GEMM, B in [K,N] via ldmatrix.trans ----------
// C = A[M,K] @ B[K,N].  mode: 1=+bias, 2=+resid(fp32), 4=relu.  C16 or C out.
// CTA 128x128, 8 warps (warp tile 32x64), K-tile 64, 3-stage cp.async,
// ONE barrier per K-tile, occupancy 2.
#define AKSTR 72                                 // A smem row stride (halfs)
#define BNSTR 136                                // B smem row stride (halfs)
#define ATILEB (128 * AKSTR * 2)                 // 18432 B
#define BTILEB (64 * BNSTR * 2)                  // 17408 B
#define STGB   (ATILEB + BTILEB)                 // 35840 B
#define TC_SMEM (3 * STGB)                       // 107520 B

__global__ void __launch_bounds__(256, 2)
tc_gemm(const __half* __restrict__ A, const __half* __restrict__ B,
        float* __restrict__ C, __half* __restrict__ C16, int M, int N, int K,
        const float* __restrict__ bias, const float* __restrict__ resid,
        int mode)
{
    extern __shared__ __half smh[];
    const uint32_t sb = smem_u32(smh);

    const int tid  = threadIdx.x;
    const int wid  = tid >> 5, lane = tid & 31;
    const int tq   = lane >> 2, tr = lane & 3;
    const int wm   = (wid & 3) * 32;
    const int wn   = (wid >> 2) * 64;
    const int m0   = blockIdx.y * 128;
    const int n0   = blockIdx.x * 128;

    const int nk = K / 64;

    uint32_t a_off[2];
    #pragma unroll
    for (int mt = 0; mt < 2; mt++) {
        const int row = wm + mt * 16 + (lane & 15);
        a_off[mt] = (uint32_t)(row * AKSTR) * 2u + ((lane >> 4) << 4);
    }
    uint32_t b_off[4];
    #pragma unroll
    for (int j = 0; j < 4; j++) {
        const int col = wn + j * 16 + ((lane >> 4) << 3);
        b_off[j] = ATILEB + (uint32_t)((lane & 15) * BNSTR + col) * 2u;
    }

    float acc[2][8][4];
    #pragma unroll
    for (int mt = 0; mt < 2; mt++)
        #pragma unroll
        for (int nt = 0; nt < 8; nt++)
            #pragma unroll
            for (int i = 0; i < 4; i++) acc[mt][nt][i] = 0.f;

    auto issue_stage = [&](int kt) {
        const uint32_t sA = sb + (uint32_t)(kt % 3) * STGB;
        const uint32_t sB = sA + ATILEB;
        const int kof = kt * 64;
        #pragma unroll
        for (int l = 0; l < 4; l++) {
            const int idx = tid + l * 256;
            const int r = idx >> 3, c = idx & 7;
            cp16(sA + (uint32_t)(r * AKSTR + c * 8) * 2u,
                 A + (size_t)(m0 + r) * K + kof + c * 8);
        }
        #pragma unroll
        for (int l = 0; l < 4; l++) {
            const int idx = tid + l * 256;
            const int r = idx >> 4, c = idx & 15;
            cp16(sB + (uint32_t)(r * BNSTR + c * 8) * 2u,
                 B + (size_t)(kof + r) * N + n0 + c * 8);
        }
        asm volatile("cp.async.commit_group;" ::: "memory");
    };

    issue_stage(0);
    issue_stage(1);

    for (int kt = 0; kt < nk; kt++) {
        if (kt < nk - 1)
            asm volatile("cp.async.wait_group 1;" ::: "memory");
        else
            asm volatile("cp.async.wait_group 0;" ::: "memory");
        __syncthreads();     // sole barrier: data ready AND prior compute done

        if (kt + 2 < nk) issue_stage(kt + 2);

        const uint32_t stg = (uint32_t)(kt % 3) * STGB;

        #pragma unroll
        for (int ks = 0; ks < 4; ks++) {
            const uint32_t akoff = stg + (uint32_t)ks * 32u;            // 16 halfs
            const uint32_t bkoff = stg + (uint32_t)ks * (16u * BNSTR * 2u);
            uint32_t a[2][4], bf[4][4];
            #pragma unroll
            for (int mt = 0; mt < 2; mt++)
                ldsm4(a[mt], sb + a_off[mt] + akoff);
            #pragma unroll
            for (int j = 0; j < 4; j++)
                ldsm4t(bf[j], sb + b_off[j] + bkoff);
            #pragma unroll
            for (int mt = 0; mt < 2; mt++)
                #pragma unroll
                for (int j = 0; j < 4; j++) {
                    mma_f16(acc[mt][2*j],   a[mt], bf[j][0], bf[j][1]);
                    mma_f16(acc[mt][2*j+1], a[mt], bf[j][2], bf[j][3]);
                }
        }
    }

    #pragma unroll
    for (int mt = 0; mt < 2; mt++) {
        const int r0 = m0 + wm + mt * 16 + tq;
        #pragma unroll
        for (int half = 0; half < 2; half++) {
            const int m = r0 + half * 8;
            #pragma unroll
            for (int nt = 0; nt < 8; nt++) {
                const int n = n0 + wn + nt * 8 + tr * 2;
                float vx = acc[mt][nt][half * 2 + 0];
                float vy = acc[mt][nt][half * 2 + 1];
                if (mode & 1) {
                    const float2 bb = *(const float2*)(bias + n);
                    vx += bb.x; vy += bb.y;
                }
                if (mode & 2) {
                    const float2 rr = *(const float2*)(resid + (size_t)m * N + n);
                    vx += rr.x; vy += rr.y;
                }
                if (mode & 4) { vx = fmaxf(vx, 0.f); vy = fmaxf(vy, 0.f); }
                if (C16) {
                    *(__half2*)(C16 + (size_t)m * N + n) = __floats2half2_rn(vx, vy);
                } else {
                    float2 o; o.x = vx; o.y = vy;
                    *(float2*)(C + (size_t)m * N + n) = o;
                }
            }
        }
    }
}

// ---------------- Flash attention: fp16 mma, Q + P in registers --------------
// 8 warps, 128 q-rows/CTA, k-tiles of 64, double-buffered K/V via cp.async.
// Q fragments hoisted to registers before the mainloop; P repacked from S accs.
#define ASH 72
#define KVBUFH (64 * ASH)
#define ATT_SMEM ((128*ASH + 2*KVBUFH + 2*KVBUFH) * 2)   // 55296 B

__global__ __launch_bounds__(256, 2)
void attn_mma_kernel(const __half* __restrict__ QKVg, __half* __restrict__ Og,
                     int ldi)
{
    extern __shared__ __half smh[];
    __half* Qs  = smh;                       // [128][72]
    __half* Ks0 = smh + 128 * ASH;           // 2 x [64][72]
    __half* Vs0 = Ks0 + 2 * KVBUFH;          // 2 x [64][72]

    const int tid  = threadIdx.x;
    const int wid  = tid >> 5, lane = tid & 31;
    const int tq   = lane >> 2, tr = lane & 3;
    const int wq0  = wid * 16;
    const int bh   = blockIdx.y;
    const int b    = bh >> 4, h = bh & 15;
    const size_t base_i = (size_t)b * SS * ldi + (size_t)h * DK;
    const size_t base_o = (size_t)b * SS * DD + (size_t)h * DK;
    const int q0   = blockIdx.x * 128;

    const __half* Qg = QKVg + base_i;
    const __half* Kg = QKVg + base_i + DD;
    const __half* Vg = QKVg + base_i + 2 * DD;

    const uint32_t sQ = smem_u32(Qs);
    const uint32_t sK = smem_u32(Ks0);
    const uint32_t sV = smem_u32(Vs0);

    const uint32_t qa = sQ + (uint32_t)((wq0 + (lane & 15)) * ASH) * 2u
                      + ((lane >> 4) << 4);
    uint32_t ka_off[4], va_off[4];
    #pragma unroll
    for (int j = 0; j < 4; j++) {
        ka_off[j] = (uint32_t)((j * 16 + (lane & 15)) * ASH) * 2u
                  + ((lane >> 4) << 4);
        va_off[j] = (uint32_t)((lane & 15) * ASH) * 2u
                  + (uint32_t)(j * 16 + ((lane >> 4) << 3)) * 2u;
    }

    // start K/V tile 0 loads first (overlap with Q staging)
    auto issue_kv = [&](int kt) {
        const uint32_t kb_ = sK + (uint32_t)(kt & 1) * (KVBUFH * 2u);
        const uint32_t vb_ = sV + (uint32_t)(kt & 1) * (KVBUFH * 2u);
        const int kb = kt * 64;
        #pragma unroll
        for (int l = 0; l < 2; l++) {
            const int idx = tid + l * 256;
            const int r = idx >> 3, c = idx & 7;
            cp16(kb_ + (uint32_t)(r * ASH + c * 8) * 2u,
                 Kg + (size_t)(kb + r) * ldi + c * 8);
        }
        #pragma unroll
        for (int l = 0; l < 2; l++) {
            const int idx = tid + l * 256;
            const int r = idx >> 3, c = idx & 7;
            cp16(vb_ + (uint32_t)(r * ASH + c * 8) * 2u,
                 Vg + (size_t)(kb + r) * ldi + c * 8);
        }
        asm volatile("cp.async.commit_group;" ::: "memory");
    };

    issue_kv(0);

    // stage Q tile to smem (scaled by exact 1/8)
    const __half2 sc2 = __float2half2_rn(0.125f);
    #pragma unroll
    for (int l = 0; l < 4; l++) {
        const int idx = tid + l * 256;
        const int r = idx >> 3, c = idx & 7;
        uint4 u = *(const uint4*)(Qg + (size_t)(q0 + r) * ldi + c * 8);
        __half2* p = (__half2*)&u;
        p[0] = __hmul2(p[0], sc2); p[1] = __hmul2(p[1], sc2);
        p[2] = __hmul2(p[2], sc2); p[3] = __hmul2(p[3], sc2);
        *(uint4*)(Qs + r * ASH + c * 8) = u;
    }
    __syncthreads();                 // Q visible to all warps

    // hoist Q fragments to registers (loop-invariant)
    uint32_t qf[4][4];
    #pragma unroll
    for (int ks = 0; ks < 4; ks++)
        ldsm4(qf[ks], qa + (uint32_t)ks * 32u);

    float m_[2], l_[2], o[8][4];
    m_[0] = m_[1] = -CUDART_INF_F;
    l_[0] = l_[1] = 0.f;
    #pragma unroll
    for (int nt = 0; nt < 8; nt++)
        #pragma unroll
        for (int i = 0; i < 4; i++) o[nt][i] = 0.f;

    const int ntiles = SS / 64;
    for (int kt = 0; kt < ntiles; kt++) {
        asm volatile("cp.async.wait_group 0;" ::: "memory");
        __syncthreads();
        if (kt + 1 < ntiles) issue_kv(kt + 1);

        const uint32_t bufb = (uint32_t)(kt & 1) * (KVBUFH * 2u);

        // S = Q @ K^T
        float s[8][4];
        #pragma unroll
        for (int nt = 0; nt < 8; nt++)
            #pragma unroll
            for (int i = 0; i < 4; i++) s[nt][i] = 0.f;

        #pragma unroll
        for (int ks = 0; ks < 4; ks++) {
            const uint32_t koff = (uint32_t)ks * 32u;
            #pragma unroll
            for (int j = 0; j < 4; j++) {
                uint32_t kf[4];
                ldsm4(kf, sK + bufb + ka_off[j] + koff);
                mma_f16(s[2*j],   qf[ks], kf[0], kf[2]);
                mma_f16(s[2*j+1], qf[ks], kf[1], kf[3]);
            }
        }

        // online softmax in fragment layout (rows tq, tq+8)
        #pragma unroll
        for (int half = 0; half < 2; half++) {
            float mx = -CUDART_INF_F;
            #pragma unroll
            for (int nt = 0; nt < 8; nt++)
                mx = fmaxf(mx, fmaxf(s[nt][half * 2], s[nt][half * 2 + 1]));
            mx = fmaxf(mx, __shfl_xor_sync(0xffffffffu, mx, 1));
            mx = fmaxf(mx, __shfl_xor_sync(0xffffffffu, mx, 2));
            const float mn   = fmaxf(m_[half], mx);
            const float corr = __expf(m_[half] - mn);
            m_[half] = mn;
            float sum = 0.f;
            #pragma unroll
            for (int nt = 0; nt < 8; nt++) {
                float p0 = __expf(s[nt][half * 2]     - mn);
                float p1 = __expf(s[nt][half * 2 + 1] - mn);
                s[nt][half * 2]     = p0;
                s[nt][half * 2 + 1] = p1;
                sum += p0 + p1;
            }
            sum += __shfl_xor_sync(0xffffffffu, sum, 1);
            sum += __shfl_xor_sync(0xffffffffu, sum, 2);
            l_[half] = l_[half] * corr + sum;
            #pragma unroll
            for (int nt = 0; nt < 8; nt++) {
                o[nt][half * 2]     *= corr;
                o[nt][half * 2 + 1] *= corr;
            }
        }

        // O += P @ V — P fragments packed directly from S accumulators
        #pragma unroll
        for (int j = 0; j < 4; j++) {
            uint32_t a[4];
            a[0] = packh2(s[2*j][0],   s[2*j][1]);
            a[1] = packh2(s[2*j][2],   s[2*j][3]);
            a[2] = packh2(s[2*j+1][0], s[2*j+1][1]);
            a[3] = packh2(s[2*j+1][2], s[2*j+1][3]);
            const uint32_t voff = bufb + (uint32_t)j * (16u * ASH * 2u);
            #pragma unroll
            for (int jj = 0; jj < 4; jj++) {
                uint32_t vf[4];
                ldsm4t(vf, sV + voff + va_off[jj]);
                mma_f16(o[2*jj],   a, vf[0], vf[1]);
                mma_f16(o[2*jj+1], a, vf[2], vf[3]);
            }
        }
    }

    const float inv0 = 1.0f / l_[0];
    const float inv1 = 1.0f / l_[1];
    #pragma unroll
    for (int nt = 0; nt < 8; nt++) {
        const int col = nt * 8 + tr * 2;
        *(__half2*)(Og + base_o + (size_t)(q0 + wq0 + tq) * DD + col) =
            __floats2half2_rn(o[nt][0] * inv0, o[nt][1] * inv0);
        *(__half2*)(Og + base_o + (size_t)(q0 + wq0 + tq + 8) * DD + col) =
            __floats2half2_rn(o[nt][2] * inv1, o[nt][3] * inv1);
    }
}

// ---------------- launch -----------------------------------------------------
extern "C" void kernel_launch(void* const* d_in, const int* in_sizes, int n_in,
                              void* d_out, int out_size)
{
    const float* X   = (const float*)d_in[0];
    const float* Wq  = (const float*)d_in[1];
    const float* Wk  = (const float*)d_in[2];
    const float* Wv  = (const float*)d_in[3];
    const float* Wo  = (const float*)d_in[4];
    const float* W1  = (const float*)d_in[5];
    const float* b1  = (const float*)d_in[6];
    const float* W2  = (const float*)d_in[7];
    const float* b2  = (const float*)d_in[8];
    const float* g1  = (const float*)d_in[9];
    const float* be1 = (const float*)d_in[10];
    const float* g2  = (const float*)d_in[11];
    const float* be2 = (const float*)d_in[12];
    float* out = (float*)d_out;

    __half *nX16, *qkv16, *ctx16, *h16, *Wqkv16, *Wo16, *W1h, *W2h;
    float *X1;
    cudaGetSymbolAddress((void**)&nX16,   g_nX16);
    cudaGetSymbolAddress((void**)&qkv16,  g_qkv16);
    cudaGetSymbolAddress((void**)&ctx16,  g_ctx16);
    cudaGetSymbolAddress((void**)&h16,    g_h16);
    cudaGetSymbolAddress((void**)&X1,     g_X1);
    cudaGetSymbolAddress((void**)&Wqkv16, g_Wqkv16);
    cudaGetSymbolAddress((void**)&Wo16,   g_Wo16);
    cudaGetSymbolAddress((void**)&W1h,    g_W1h);
    cudaGetSymbolAddress((void**)&W2h,    g_W2h);

    cudaFuncSetAttribute(tc_gemm, cudaFuncAttributeMaxDynamicSharedMemorySize,
                         TC_SMEM);
    cudaFuncSetAttribute(attn_mma_kernel,
                         cudaFuncAttributeMaxDynamicSharedMemorySize, ATT_SMEM);

    dim3 thr(256);

    // 1: single fused weight convert
    convert_all_kernel<<<2048, thr>>>(Wq, Wk, Wv, Wo, W1, W2,
                                      Wqkv16, Wo16, W1h, W2h);

    // 2: LN1
    ln_kernel<<<MR, thr>>>(X, g1, be1, nX16);

    // 3: fused QKV projection
    tc_gemm<<<dim3(QKVN/128, MR/128), thr, TC_SMEM>>>(
        nX16, Wqkv16, nullptr, qkv16, MR, QKVN, DD, nullptr, nullptr, 0);

    // 4: attention
    attn_mma_kernel<<<dim3(SS/128, BB*HH), thr, ATT_SMEM>>>(qkv16, ctx16, QKVN);

    // 5: output projection + residual -> X1 fp32
    tc_gemm<<<dim3(DD/128, MR/128), thr, TC_SMEM>>>(
        ctx16, Wo16, X1, nullptr, MR, DD, DD, nullptr, X, 2);

    // 6: LN2
    ln_kernel<<<MR, thr>>>(X1, g2, be2, nX16);

    // 7: FFN up
    tc_gemm<<<dim3(FF/128, MR/128), thr, TC_SMEM>>>(
        nX16, W1h, nullptr, h16, MR, FF, DD, b1, nullptr, 1 | 4);

    // 8: FFN down + residual
    tc_gemm<<<dim3(DD/128, MR/128), thr, TC_SMEM>>>(
        h16, W2h, out, nullptr, MR, DD, FF, b2, X1, 1 | 2);
}

// round 16
// speedup vs baseline: 1.5359x; 1.5359x over previous
#include <cuda_runtime.h>
#include <cuda_fp16.h>
#include <math_constants.h>
#include <cstdint>

// Problem constants
#define BB 2
#define SS 2048
#define DD 1024
#define HH 16
#define DK 64
#define FF 4096
#define MR (BB*SS)          // 4096 rows
#define QKVN 3072

// ---------------- scratch (static device globals: alloc-free rule) ----------
__device__ __half g_nX16  [MR*DD];
__device__ __half g_qkv16 [(size_t)MR*QKVN];
__device__ __half g_ctx16 [MR*DD];
__device__ __half g_h16   [(size_t)MR*FF];
__device__ float  g_X1    [MR*DD];
__device__ __half g_Wqkv16[(size_t)DD*QKVN];   // [K=1024, N=3072] interleaved
__device__ __half g_Wo16  [DD*DD];             // [K=1024, N=1024]
__device__ __half g_W1h   [(size_t)DD*FF];     // [K=1024, N=4096]
__device__ __half g_W2h   [(size_t)FF*DD];     // [K=4096, N=1024]

// ---------------- small helpers ---------------------------------------------
__device__ __forceinline__ uint32_t smem_u32(const void* p) {
    uint32_t a;
    asm("{ .reg .u64 t; cvta.to.shared.u64 t, %1; cvt.u32.u64 %0, t; }"
        : "=r"(a) : "l"(p));
    return a;
}
__device__ __forceinline__ void cp16(uint32_t s, const void* g) {
    asm volatile("cp.async.cg.shared.global [%0], [%1], 16;" :: "r"(s), "l"(g));
}
__device__ __forceinline__ void ldsm4(uint32_t* r, uint32_t addr) {
    asm volatile(
        "ldmatrix.sync.aligned.m8n8.x4.shared.b16 {%0,%1,%2,%3}, [%4];"
        : "=r"(r[0]), "=r"(r[1]), "=r"(r[2]), "=r"(r[3]) : "r"(addr));
}
__device__ __forceinline__ void ldsm4t(uint32_t* r, uint32_t addr) {
    asm volatile(
        "ldmatrix.sync.aligned.m8n8.x4.trans.shared.b16 {%0,%1,%2,%3}, [%4];"
        : "=r"(r[0]), "=r"(r[1]), "=r"(r[2]), "=r"(r[3]) : "r"(addr));
}
__device__ __forceinline__ void mma_f16(float* c, const uint32_t* a,
                                        uint32_t b0, uint32_t b1) {
    asm volatile(
        "mma.sync.aligned.m16n8k16.row.col.f32.f16.f16.f32 "
        "{%0,%1,%2,%3}, {%4,%5,%6,%7}, {%8,%9}, {%0,%1,%2,%3};"
        : "+f"(c[0]), "+f"(c[1]), "+f"(c[2]), "+f"(c[3])
        : "r"(a[0]), "r"(a[1]), "r"(a[2]), "r"(a[3]), "r"(b0), "r"(b1));
}
__device__ __forceinline__ uint32_t packh2(float x, float y) {
    __half2 h = __floats2half2_rn(x, y);
    return *(uint32_t*)&h;
}

// ---------------- single fused weight convert (fp32 -> fp16) -----------------
__global__ __launch_bounds__(256)
void convert_all_kernel(const float* __restrict__ wq, const float* __restrict__ wk,
                        const float* __restrict__ wv, const float* __restrict__ wo,
                        const float* __restrict__ w1, const float* __restrict__ w2,
                        __half* __restrict__ oqkv, __half* __restrict__ owo,
                        __half* __restrict__ ow1, __half* __restrict__ ow2)
{
    const int per = DD * DD / 4;                   // float4s per DDxDD matrix
    const int nqkv = 3 * per;
    const int nw1  = DD * FF / 4;
    const int nw2  = FF * DD / 4;
    const int tot  = nqkv + per + nw1 + nw2;
    for (int idx = blockIdx.x * 256 + threadIdx.x; idx < tot;
         idx += gridDim.x * 256) {
        float4 val;
        __half2* o;
        if (idx < nqkv) {
            const int m   = idx / per;
            const int rem = idx - m * per;
            const int r   = rem >> 8;
            const int c4  = (rem & 255) << 2;
            const float* src = (m == 0 ? wq : m == 1 ? wk : wv)
                             + (size_t)r * DD + c4;
            val = *(const float4*)src;
            o = (__half2*)(oqkv + (size_t)r * QKVN + m * DD + c4);
        } else {
            int i = idx - nqkv;
            const float* src;
            __half* dst;
            if (i < per)               { src = wo; dst = owo; }
            else if ((i -= per) < nw1) { src = w1; dst = ow1; }
            else                       { i -= nw1; src = w2; dst = ow2; }
            val = *(const float4*)(src + (size_t)i * 4);
            o = (__half2*)(dst + (size_t)i * 4);
        }
        o[0] = __floats2half2_rn(val.x, val.y);
        o[1] = __floats2half2_rn(val.z, val.w);
    }
}

// ---------------- LayerNorm (fp32 in, fp16 out) ------------------------------
__global__ __launch_bounds__(256)
void ln_kernel(const float* __restrict__ X, const float* __restrict__ g,
               const float* __restrict__ b, __half* __restrict__ Y)
{
    const int row = blockIdx.x;
    const int tid = threadIdx.x;
    const float4 x = ((const float4*)(X + (size_t)row * DD))[tid];

    float s  = x.x + x.y + x.z + x.w;
    float ss = x.x*x.x + x.y*x.y + x.z*x.z + x.w*x.w;
    #pragma unroll
    for (int o = 16; o; o >>= 1) {
        s  += __shfl_xor_sync(0xffffffffu, s,  o);
        ss += __shfl_xor_sync(0xffffffffu, ss, o);
    }
    __shared__ float sw[8], sw2[8];
    const int w = tid >> 5, ln = tid & 31;
    if (ln == 0) { sw[w] = s; sw2[w] = ss; }
    __syncthreads();
    float tot = 0.f, tot2 = 0.f;
    #pragma unroll
    for (int i = 0; i < 8; i++) { tot += sw[i]; tot2 += sw2[i]; }

    const float mean = tot * (1.0f / DD);
    const float var  = tot2 * (1.0f / DD) - mean * mean;
    const float rstd = rsqrtf(var + 1e-5f);

    const float4 gv = ((const float4*)g)[tid];
    const float4 bv = ((const float4*)b)[tid];
    __half2 h01 = __floats2half2_rn((x.x - mean) * rstd * gv.x + bv.x,
                                    (x.y - mean) * rstd * gv.y + bv.y);
    __half2 h23 = __floats2half2_rn((x.z - mean) * rstd * gv.z + bv.z,
                                    (x.w - mean) * rstd * gv.w + bv.w);
    __half2* yp = (__half2*)(Y + (size_t)row * DD + tid * 4);
    yp[0] = h01; yp[1] = h23;
}

// ---------------- fp16 mma.sync GEMM, B in [K,N] via ldmatrix.trans ----------
// C = A[M,K] @ B[K,N].  mode: 1=+bias, 2=+resid(fp32), 4=relu.  C16 or C out.
// CTA 128x128, 8 warps (warp tile 32x64), K-tile 64, 3-stage cp.async,
// ONE barrier per K-tile, occupancy 2.
#define AKSTR 72                                 // A smem row stride (halfs)
#define BNSTR 136                                // B smem row stride (halfs)
#define ATILEB (128 * AKSTR * 2)                 // 18432 B
#define BTILEB (64 * BNSTR * 2)                  // 17408 B
#define STGB   (ATILEB + BTILEB)                 // 35840 B
#define TC_SMEM (3 * STGB)                       // 107520 B

__global__ void __launch_bounds__(256, 2)
tc_gemm(const __half* __restrict__ A, const __half* __restrict__ B,
        float* __restrict__ C, __half* __restrict__ C16, int M, int N, int K,
        const float* __restrict__ bias, const float* __restrict__ resid,
        int mode)
{
    extern __shared__ __half smh[];
    const uint32_t sb = smem_u32(smh);

    const int tid  = threadIdx.x;
    const int wid  = tid >> 5, lane = tid & 31;
    const int tq   = lane >> 2, tr = lane & 3;
    const int wm   = (wid & 3) * 32;
    const int wn   = (wid >> 2) * 64;
    const int m0   = blockIdx.y * 128;
    const int n0   = blockIdx.x * 128;

    const int nk = K / 64;

    uint32_t a_off[2];
    #pragma unroll
    for (int mt = 0; mt < 2; mt++) {
        const int row = wm + mt * 16 + (lane & 15);
        a_off[mt] = (uint32_t)(row * AKSTR) * 2u + ((lane >> 4) << 4);
    }
    uint32_t b_off[4];
    #pragma unroll
    for (int j = 0; j < 4; j++) {
        const int col = wn + j * 16 + ((lane >> 4) << 3);
        b_off[j] = ATILEB + (uint32_t)((lane & 15) * BNSTR + col) * 2u;
    }

    float acc[2][8][4];
    #pragma unroll
    for (int mt = 0; mt < 2; mt++)
        #pragma unroll
        for (int nt = 0; nt < 8; nt++)
            #pragma unroll
            for (int i = 0; i < 4; i++) acc[mt][nt][i] = 0.f;

    auto issue_stage = [&](int kt) {
        const uint32_t sA = sb + (uint32_t)(kt % 3) * STGB;
        const uint32_t sB = sA + ATILEB;
        const int kof = kt * 64;
        #pragma unroll
        for (int l = 0; l < 4; l++) {
            const int idx = tid + l * 256;
            const int r = idx >> 3, c = idx & 7;
            cp16(sA + (uint32_t)(r * AKSTR + c * 8) * 2u,
                 A + (size_t)(m0 + r) * K + kof + c * 8);
        }
        #pragma unroll
        for (int l = 0; l < 4; l++) {
            const int idx = tid + l * 256;
            const int r = idx >> 4, c = idx & 15;
            cp16(sB + (uint32_t)(r * BNSTR + c * 8) * 2u,
                 B + (size_t)(kof + r) * N + n0 + c * 8);
        }
        asm volatile("cp.async.commit_group;" ::: "memory");
    };

    issue_stage(0);
    issue_stage(1);

    for (int kt = 0; kt < nk; kt++) {
        if (kt < nk - 1)
            asm volatile("cp.async.wait_group 1;" ::: "memory");
        else
            asm volatile("cp.async.wait_group 0;" ::: "memory");
        __syncthreads();     // sole barrier: data ready AND prior compute done

        if (kt + 2 < nk) issue_stage(kt + 2);

        const uint32_t stg = (uint32_t)(kt % 3) * STGB;

        #pragma unroll
        for (int ks = 0; ks < 4; ks++) {
            const uint32_t akoff = stg + (uint32_t)ks * 32u;            // 16 halfs
            const uint32_t bkoff = stg + (uint32_t)ks * (16u * BNSTR * 2u);
            uint32_t a[2][4], bf[4][4];
            #pragma unroll
            for (int mt = 0; mt < 2; mt++)
                ldsm4(a[mt], sb + a_off[mt] + akoff);
            #pragma unroll
            for (int j = 0; j < 4; j++)
                ldsm4t(bf[j], sb + b_off[j] + bkoff);
            #pragma unroll
            for (int mt = 0; mt < 2; mt++)
                #pragma unroll
                for (int j = 0; j < 4; j++) {
                    mma_f16(acc[mt][2*j],   a[mt], bf[j][0], bf[j][1]);
                    mma_f16(acc[mt][2*j+1], a[mt], bf[j][2], bf[j][3]);
                }
        }
    }

    #pragma unroll
    for (int mt = 0; mt < 2; mt++) {
        const int r0 = m0 + wm + mt * 16 + tq;
        #pragma unroll
        for (int half = 0; half < 2; half++) {
            const int m = r0 + half * 8;
            #pragma unroll
            for (int nt = 0; nt < 8; nt++) {
                const int n = n0 + wn + nt * 8 + tr * 2;
                float vx = acc[mt][nt][half * 2 + 0];
                float vy = acc[mt][nt][half * 2 + 1];
                if (mode & 1) {
                    const float2 bb = *(const float2*)(bias + n);
                    vx += bb.x; vy += bb.y;
                }
                if (mode & 2) {
                    const float2 rr = *(const float2*)(resid + (size_t)m * N + n);
                    vx += rr.x; vy += rr.y;
                }
                if (mode & 4) { vx = fmaxf(vx, 0.f); vy = fmaxf(vy, 0.f); }
                if (C16) {
                    *(__half2*)(C16 + (size_t)m * N + n) = __floats2half2_rn(vx, vy);
                } else {
                    float2 o; o.x = vx; o.y = vy;
                    *(float2*)(C + (size_t)m * N + n) = o;
                }
            }
        }
    }
}

// ---------------- Flash attention: fp16 mma, P kept in registers -------------
// (R13-proven version: Q fragments re-read from smem each k-tile; no spills.)
#define ASH 72
#define KVBUFH (64 * ASH)
#define ATT_SMEM ((128*ASH + 2*KVBUFH + 2*KVBUFH) * 2)   // 55296 B

__global__ __launch_bounds__(256, 2)
void attn_mma_kernel(const __half* __restrict__ QKVg, __half* __restrict__ Og,
                     int ldi)
{
    extern __shared__ __half smh[];
    __half* Qs  = smh;                       // [128][72]
    __half* Ks0 = smh + 128 * ASH;           // 2 x [64][72]
    __half* Vs0 = Ks0 + 2 * KVBUFH;          // 2 x [64][72]

    const int tid  = threadIdx.x;
    const int wid  = tid >> 5, lane = tid & 31;
    const int tq   = lane >> 2, tr = lane & 3;
    const int wq0  = wid * 16;
    const int bh   = blockIdx.y;
    const int b    = bh >> 4, h = bh & 15;
    const size_t base_i = (size_t)b * SS * ldi + (size_t)h * DK;
    const size_t base_o = (size_t)b * SS * DD + (size_t)h * DK;
    const int q0   = blockIdx.x * 128;

    const __half* Qg = QKVg + base_i;
    const __half* Kg = QKVg + base_i + DD;
    const __half* Vg = QKVg + base_i + 2 * DD;

    const uint32_t sQ = smem_u32(Qs);
    const uint32_t sK = smem_u32(Ks0);
    const uint32_t sV = smem_u32(Vs0);

    const uint32_t qa = sQ + (uint32_t)((wq0 + (lane & 15)) * ASH) * 2u
                      + ((lane >> 4) << 4);
    uint32_t ka_off[4], va_off[4];
    #pragma unroll
    for (int j = 0; j < 4; j++) {
        ka_off[j] = (uint32_t)((j * 16 + (lane & 15)) * ASH) * 2u
                  + ((lane >> 4) << 4);
        va_off[j] = (uint32_t)((lane & 15) * ASH) * 2u
                  + (uint32_t)(j * 16 + ((lane >> 4) << 3)) * 2u;
    }

    // load Q tile (scaled by exact 1/8)
    const __half2 sc2 = __float2half2_rn(0.125f);
    #pragma unroll
    for (int l = 0; l < 4; l++) {
        const int idx = tid + l * 256;
        const int r = idx >> 3, c = idx & 7;
        uint4 u = *(const uint4*)(Qg + (size_t)(q0 + r) * ldi + c * 8);
        __half2* p = (__half2*)&u;
        p[0] = __hmul2(p[0], sc2); p[1] = __hmul2(p[1], sc2);
        p[2] = __hmul2(p[2], sc2); p[3] = __hmul2(p[3], sc2);
        *(uint4*)(Qs + r * ASH + c * 8) = u;
    }

    auto issue_kv = [&](int kt) {
        const uint32_t kb_ = sK + (uint32_t)(kt & 1) * (KVBUFH * 2u);
        const uint32_t vb_ = sV + (uint32_t)(kt & 1) * (KVBUFH * 2u);
        const int kb = kt * 64;
        #pragma unroll
        for (int l = 0; l < 2; l++) {
            const int idx = tid + l * 256;
            const int r = idx >> 3, c = idx & 7;
            cp16(kb_ + (uint32_t)(r * ASH + c * 8) * 2u,
                 Kg + (size_t)(kb + r) * ldi + c * 8);
        }
        #pragma unroll
        for (int l = 0; l < 2; l++) {
            const int idx = tid + l * 256;
            const int r = idx >> 3, c = idx & 7;
            cp16(vb_ + (uint32_t)(r * ASH + c * 8) * 2u,
                 Vg + (size_t)(kb + r) * ldi + c * 8);
        }
        asm volatile("cp.async.commit_group;" ::: "memory");
    };

    issue_kv(0);

    float m_[2], l_[2], o[8][4];
    m_[0] = m_[1] = -CUDART_INF_F;
    l_[0] = l_[1] = 0.f;
    #pragma unroll
    for (int nt = 0; nt < 8; nt++)
        #pragma unroll
        for (int i = 0; i < 4; i++) o[nt][i] = 0.f;

    const int ntiles = SS / 64;
    for (int kt = 0; kt < ntiles; kt++) {
        asm volatile("cp.async.wait_group 0;" ::: "memory");
        __syncthreads();
        if (kt + 1 < ntiles) issue_kv(kt + 1);

        const uint32_t bufb = (uint32_t)(kt & 1) * (KVBUFH * 2u);

        // S = Q @ K^T
        float s[8][4];
        #pragma unroll
        for (int nt = 0; nt < 8; nt++)
            #pragma unroll
            for (int i = 0; i < 4; i++) s[nt][i] = 0.f;

        #pragma unroll
        for (int ks = 0; ks < 4; ks++) {
            const uint32_t koff = (uint32_t)ks * 32u;
            uint32_t a[4];
            ldsm4(a, qa + koff);
            #pragma unroll
            for (int j = 0; j < 4; j++) {
                uint32_t kf[4];
                ldsm4(kf, sK + bufb + ka_off[j] + koff);
                mma_f16(s[2*j],   a, kf[0], kf[2]);
                mma_f16(s[2*j+1], a, kf[1], kf[3]);
            }
        }

        // online softmax in fragment layout (rows tq, tq+8)
        #pragma unroll
        for (int half = 0; half < 2; half++) {
            float mx = -CUDART_INF_F;
            #pragma unroll
            for (int nt = 0; nt < 8; nt++)
                mx = fmaxf(mx, fmaxf(s[nt][half * 2], s[nt][half * 2 + 1]));
            mx = fmaxf(mx, __shfl_xor_sync(0xffffffffu, mx, 1));
            mx = fmaxf(mx, __shfl_xor_sync(0xffffffffu, mx, 2));
            const float mn   = fmaxf(m_[half], mx);
            const float corr = __expf(m_[half] - mn);
            m_[half] = mn;
            float sum = 0.f;
            #pragma unroll
            for (int nt = 0; nt < 8; nt++) {
                float p0 = __expf(s[nt][half * 2]     - mn);
                float p1 = __expf(s[nt][half * 2 + 1] - mn);
                s[nt][half * 2]     = p0;
                s[nt][half * 2 + 1] = p1;
                sum += p0 + p1;
            }
            sum += __shfl_xor_sync(0xffffffffu, sum, 1);
            sum += __shfl_xor_sync(0xffffffffu, sum, 2);
            l_[half] = l_[half] * corr + sum;
            #pragma unroll
            for (int nt = 0; nt < 8; nt++) {
                o[nt][half * 2]     *= corr;
                o[nt][half * 2 + 1] *= corr;
            }
        }

        // O += P @ V — P fragments packed directly from S accumulators
        #pragma unroll
        for (int j = 0; j < 4; j++) {
            uint32_t a[4];
            a[0] = packh2(s[2*j][0],   s[2*j][1]);
            a[1] = packh2(s[2*j][2],   s[2*j][3]);
            a[2] = packh2(s[2*j+1][0], s[2*j+1][1]);
            a[3] = packh2(s[2*j+1][2], s[2*j+1][3]);
            const uint32_t voff = bufb + (uint32_t)j * (16u * ASH * 2u);
            #pragma unroll
            for (int jj = 0; jj < 4; jj++) {
                uint32_t vf[4];
                ldsm4t(vf, sV + voff + va_off[jj]);
                mma_f16(o[2*jj],   a, vf[0], vf[1]);
                mma_f16(o[2*jj+1], a, vf[2], vf[3]);
            }
        }
    }

    const float inv0 = 1.0f / l_[0];
    const float inv1 = 1.0f / l_[1];
    #pragma unroll
    for (int nt = 0; nt < 8; nt++) {
        const int col = nt * 8 + tr * 2;
        *(__half2*)(Og + base_o + (size_t)(q0 + wq0 + tq) * DD + col) =
            __floats2half2_rn(o[nt][0] * inv0, o[nt][1] * inv0);
        *(__half2*)(Og + base_o + (size_t)(q0 + wq0 + tq + 8) * DD + col) =
            __floats2half2_rn(o[nt][2] * inv1, o[nt][3] * inv1);
    }
}

// ---------------- launch -----------------------------------------------------
extern "C" void kernel_launch(void* const* d_in, const int* in_sizes, int n_in,
                              void* d_out, int out_size)
{
    const float* X   = (const float*)d_in[0];
    const float* Wq  = (const float*)d_in[1];
    const float* Wk  = (const float*)d_in[2];
    const float* Wv  = (const float*)d_in[3];
    const float* Wo  = (const float*)d_in[4];
    const float* W1  = (const float*)d_in[5];
    const float* b1  = (const float*)d_in[6];
    const float* W2  = (const float*)d_in[7];
    const float* b2  = (const float*)d_in[8];
    const float* g1  = (const float*)d_in[9];
    const float* be1 = (const float*)d_in[10];
    const float* g2  = (const float*)d_in[11];
    const float* be2 = (const float*)d_in[12];
    float* out = (float*)d_out;

    __half *nX16, *qkv16, *ctx16, *h16, *Wqkv16, *Wo16, *W1h, *W2h;
    float *X1;
    cudaGetSymbolAddress((void**)&nX16,   g_nX16);
    cudaGetSymbolAddress((void**)&qkv16,  g_qkv16);
    cudaGetSymbolAddress((void**)&ctx16,  g_ctx16);
    cudaGetSymbolAddress((void**)&h16,    g_h16);
    cudaGetSymbolAddress((void**)&X1,     g_X1);
    cudaGetSymbolAddress((void**)&Wqkv16, g_Wqkv16);
    cudaGetSymbolAddress((void**)&Wo16,   g_Wo16);
    cudaGetSymbolAddress((void**)&W1h,    g_W1h);
    cudaGetSymbolAddress((void**)&W2h,    g_W2h);

    cudaFuncSetAttribute(tc_gemm, cudaFuncAttributeMaxDynamicSharedMemorySize,
                         TC_SMEM);
    cudaFuncSetAttribute(attn_mma_kernel,
                         cudaFuncAttributeMaxDynamicSharedMemorySize, ATT_SMEM);

    dim3 thr(256);

    // 1: single fused weight convert
    convert_all_kernel<<<2048, thr>>>(Wq, Wk, Wv, Wo, W1, W2,
                                      Wqkv16, Wo16, W1h, W2h);

    // 2: LN1
    ln_kernel<<<MR, thr>>>(X, g1, be1, nX16);

    // 3: fused QKV projection
    tc_gemm<<<dim3(QKVN/128, MR/128), thr, TC_SMEM>>>(
        nX16, Wqkv16, nullptr, qkv16, MR, QKVN, DD, nullptr, nullptr, 0);

    // 4: attention
    attn_mma_kernel<<<dim3(SS/128, BB*HH), thr, ATT_SMEM>>>(qkv16, ctx16, QKVN);

    // 5: output projection + residual -> X1 fp32
    tc_gemm<<<dim3(DD/128, MR/128), thr, TC_SMEM>>>(
        ctx16, Wo16, X1, nullptr, MR, DD, DD, nullptr, X, 2);

    // 6: LN2
    ln_kernel<<<MR, thr>>>(X1, g2, be2, nX16);

    // 7: FFN up
    tc_gemm<<<dim3(FF/128, MR/128), thr, TC_SMEM>>>(
        nX16, W1h, nullptr, h16, MR, FF, DD, b1, nullptr, 1 | 4);

    // 8: FFN down + residual
    tc_gemm<<<dim3(DD/128, MR/128), thr, TC_SMEM>>>(
        h16, W2h, out, nullptr, MR, DD, FF, b2, X1, 1 | 2);
}

// round 17
// speedup vs baseline: 1.5535x; 1.0114x over previous
#include <cuda_runtime.h>
#include <cuda_fp16.h>
#include <math_constants.h>
#include <cstdint>

// Problem constants
#define BB 2
#define SS 2048
#define DD 1024
#define HH 16
#define DK 64
#define FF 4096
#define MR (BB*SS)          // 4096 rows
#define QKVN 3072

// ---------------- scratch (static device globals: alloc-free rule) ----------
__device__ __half g_nX16  [MR*DD];
__device__ __half g_qkv16 [(size_t)MR*QKVN];
__device__ __half g_ctx16 [MR*DD];
__device__ __half g_h16   [(size_t)MR*FF];
__device__ float  g_X1    [MR*DD];
__device__ __half g_Wqkv16[(size_t)DD*QKVN];   // [K=1024, N=3072] interleaved
__device__ __half g_Wo16  [DD*DD];             // [K=1024, N=1024]
__device__ __half g_W1h   [(size_t)DD*FF];     // [K=1024, N=4096]
__device__ __half g_W2h   [(size_t)FF*DD];     // [K=4096, N=1024]

// ---------------- small helpers ---------------------------------------------
__device__ __forceinline__ uint32_t smem_u32(const void* p) {
    uint32_t a;
    asm("{ .reg .u64 t; cvta.to.shared.u64 t, %1; cvt.u32.u64 %0, t; }"
        : "=r"(a) : "l"(p));
    return a;
}
__device__ __forceinline__ void cp16(uint32_t s, const void* g) {
    asm volatile("cp.async.cg.shared.global [%0], [%1], 16;" :: "r"(s), "l"(g));
}
__device__ __forceinline__ void ldsm4(uint32_t* r, uint32_t addr) {
    asm volatile(
        "ldmatrix.sync.aligned.m8n8.x4.shared.b16 {%0,%1,%2,%3}, [%4];"
        : "=r"(r[0]), "=r"(r[1]), "=r"(r[2]), "=r"(r[3]) : "r"(addr));
}
__device__ __forceinline__ void ldsm4t(uint32_t* r, uint32_t addr) {
    asm volatile(
        "ldmatrix.sync.aligned.m8n8.x4.trans.shared.b16 {%0,%1,%2,%3}, [%4];"
        : "=r"(r[0]), "=r"(r[1]), "=r"(r[2]), "=r"(r[3]) : "r"(addr));
}
__device__ __forceinline__ void mma_f16(float* c, const uint32_t* a,
                                        uint32_t b0, uint32_t b1) {
    asm volatile(
        "mma.sync.aligned.m16n8k16.row.col.f32.f16.f16.f32 "
        "{%0,%1,%2,%3}, {%4,%5,%6,%7}, {%8,%9}, {%0,%1,%2,%3};"
        : "+f"(c[0]), "+f"(c[1]), "+f"(c[2]), "+f"(c[3])
        : "r"(a[0]), "r"(a[1]), "r"(a[2]), "r"(a[3]), "r"(b0), "r"(b1));
}
__device__ __forceinline__ uint32_t packh2(float x, float y) {
    __half2 h = __floats2half2_rn(x, y);
    return *(uint32_t*)&h;
}
// bare hardware exp2 (same MUFU op __expf uses after its mul)
__device__ __forceinline__ float ex2f(float x) {
    float y;
    asm("ex2.approx.f32 %0, %1;" : "=f"(y) : "f"(x));
    return y;
}

// ---------------- single fused weight convert (fp32 -> fp16) -----------------
__global__ __launch_bounds__(256)
void convert_all_kernel(const float* __restrict__ wq, const float* __restrict__ wk,
                        const float* __restrict__ wv, const float* __restrict__ wo,
                        const float* __restrict__ w1, const float* __restrict__ w2,
                        __half* __restrict__ oqkv, __half* __restrict__ owo,
                        __half* __restrict__ ow1, __half* __restrict__ ow2)
{
    const int per = DD * DD / 4;                   // float4s per DDxDD matrix
    const int nqkv = 3 * per;
    const int nw1  = DD * FF / 4;
    const int nw2  = FF * DD / 4;
    const int tot  = nqkv + per + nw1 + nw2;
    for (int idx = blockIdx.x * 256 + threadIdx.x; idx < tot;
         idx += gridDim.x * 256) {
        float4 val;
        __half2* o;
        if (idx < nqkv) {
            const int m   = idx / per;
            const int rem = idx - m * per;
            const int r   = rem >> 8;
            const int c4  = (rem & 255) << 2;
            const float* src = (m == 0 ? wq : m == 1 ? wk : wv)
                             + (size_t)r * DD + c4;
            val = *(const float4*)src;
            o = (__half2*)(oqkv + (size_t)r * QKVN + m * DD + c4);
        } else {
            int i = idx - nqkv;
            const float* src;
            __half* dst;
            if (i < per)               { src = wo; dst = owo; }
            else if ((i -= per) < nw1) { src = w1; dst = ow1; }
            else                       { i -= nw1; src = w2; dst = ow2; }
            val = *(const float4*)(src + (size_t)i * 4);
            o = (__half2*)(dst + (size_t)i * 4);
        }
        o[0] = __floats2half2_rn(val.x, val.y);
        o[1] = __floats2half2_rn(val.z, val.w);
    }
}

// ---------------- LayerNorm (fp32 in, fp16 out) ------------------------------
__global__ __launch_bounds__(256)
void ln_kernel(const float* __restrict__ X, const float* __restrict__ g,
               const float* __restrict__ b, __half* __restrict__ Y)
{
    const int row = blockIdx.x;
    const int tid = threadIdx.x;
    const float4 x = ((const float4*)(X + (size_t)row * DD))[tid];

    float s  = x.x + x.y + x.z + x.w;
    float ss = x.x*x.x + x.y*x.y + x.z*x.z + x.w*x.w;
    #pragma unroll
    for (int o = 16; o; o >>= 1) {
        s  += __shfl_xor_sync(0xffffffffu, s,  o);
        ss += __shfl_xor_sync(0xffffffffu, ss, o);
    }
    __shared__ float sw[8], sw2[8];
    const int w = tid >> 5, ln = tid & 31;
    if (ln == 0) { sw[w] = s; sw2[w] = ss; }
    __syncthreads();
    float tot = 0.f, tot2 = 0.f;
    #pragma unroll
    for (int i = 0; i < 8; i++) { tot += sw[i]; tot2 += sw2[i]; }

    const float mean = tot * (1.0f / DD);
    const float var  = tot2 * (1.0f / DD) - mean * mean;
    const float rstd = rsqrtf(var + 1e-5f);

    const float4 gv = ((const float4*)g)[tid];
    const float4 bv = ((const float4*)b)[tid];
    __half2 h01 = __floats2half2_rn((x.x - mean) * rstd * gv.x + bv.x,
                                    (x.y - mean) * rstd * gv.y + bv.y);
    __half2 h23 = __floats2half2_rn((x.z - mean) * rstd * gv.z + bv.z,
                                    (x.w - mean) * rstd * gv.w + bv.w);
    __half2* yp = (__half2*)(Y + (size_t)row * DD + tid * 4);
    yp[0] = h01; yp[1] = h23;
}

// ---------------- fp16 mma.sync GEMM, B in [K,N] via ldmatrix.trans ----------
// C = A[M,K] @ B[K,N].  mode: 1=+bias, 2=+resid(fp32), 4=relu.  C16 or C out.
// CTA 128x128, 8 warps (warp tile 32x64), K-tile 64, 3-stage cp.async,
// ONE barrier per K-tile, occupancy 2.
#define AKSTR 72                                 // A smem row stride (halfs)
#define BNSTR 136                                // B smem row stride (halfs)
#define ATILEB (128 * AKSTR * 2)                 // 18432 B
#define BTILEB (64 * BNSTR * 2)                  // 17408 B
#define STGB   (ATILEB + BTILEB)                 // 35840 B
#define TC_SMEM (3 * STGB)                       // 107520 B

__global__ void __launch_bounds__(256, 2)
tc_gemm(const __half* __restrict__ A, const __half* __restrict__ B,
        float* __restrict__ C, __half* __restrict__ C16, int M, int N, int K,
        const float* __restrict__ bias, const float* __restrict__ resid,
        int mode)
{
    extern __shared__ __half smh[];
    const uint32_t sb = smem_u32(smh);

    const int tid  = threadIdx.x;
    const int wid  = tid >> 5, lane = tid & 31;
    const int tq   = lane >> 2, tr = lane & 3;
    const int wm   = (wid & 3) * 32;
    const int wn   = (wid >> 2) * 64;
    const int m0   = blockIdx.y * 128;
    const int n0   = blockIdx.x * 128;

    const int nk = K / 64;

    uint32_t a_off[2];
    #pragma unroll
    for (int mt = 0; mt < 2; mt++) {
        const int row = wm + mt * 16 + (lane & 15);
        a_off[mt] = (uint32_t)(row * AKSTR) * 2u + ((lane >> 4) << 4);
    }
    uint32_t b_off[4];
    #pragma unroll
    for (int j = 0; j < 4; j++) {
        const int col = wn + j * 16 + ((lane >> 4) << 3);
        b_off[j] = ATILEB + (uint32_t)((lane & 15) * BNSTR + col) * 2u;
    }

    float acc[2][8][4];
    #pragma unroll
    for (int mt = 0; mt < 2; mt++)
        #pragma unroll
        for (int nt = 0; nt < 8; nt++)
            #pragma unroll
            for (int i = 0; i < 4; i++) acc[mt][nt][i] = 0.f;

    auto issue_stage = [&](int kt) {
        const uint32_t sA = sb + (uint32_t)(kt % 3) * STGB;
        const uint32_t sB = sA + ATILEB;
        const int kof = kt * 64;
        #pragma unroll
        for (int l = 0; l < 4; l++) {
            const int idx = tid + l * 256;
            const int r = idx >> 3, c = idx & 7;
            cp16(sA + (uint32_t)(r * AKSTR + c * 8) * 2u,
                 A + (size_t)(m0 + r) * K + kof + c * 8);
        }
        #pragma unroll
        for (int l = 0; l < 4; l++) {
            const int idx = tid + l * 256;
            const int r = idx >> 4, c = idx & 15;
            cp16(sB + (uint32_t)(r * BNSTR + c * 8) * 2u,
                 B + (size_t)(kof + r) * N + n0 + c * 8);
        }
        asm volatile("cp.async.commit_group;" ::: "memory");
    };

    issue_stage(0);
    issue_stage(1);

    for (int kt = 0; kt < nk; kt++) {
        if (kt < nk - 1)
            asm volatile("cp.async.wait_group 1;" ::: "memory");
        else
            asm volatile("cp.async.wait_group 0;" ::: "memory");
        __syncthreads();     // sole barrier: data ready AND prior compute done

        if (kt + 2 < nk) issue_stage(kt + 2);

        const uint32_t stg = (uint32_t)(kt % 3) * STGB;

        #pragma unroll
        for (int ks = 0; ks < 4; ks++) {
            const uint32_t akoff = stg + (uint32_t)ks * 32u;            // 16 halfs
            const uint32_t bkoff = stg + (uint32_t)ks * (16u * BNSTR * 2u);
            uint32_t a[2][4], bf[4][4];
            #pragma unroll
            for (int mt = 0; mt < 2; mt++)
                ldsm4(a[mt], sb + a_off[mt] + akoff);
            #pragma unroll
            for (int j = 0; j < 4; j++)
                ldsm4t(bf[j], sb + b_off[j] + bkoff);
            #pragma unroll
            for (int mt = 0; mt < 2; mt++)
                #pragma unroll
                for (int j = 0; j < 4; j++) {
                    mma_f16(acc[mt][2*j],   a[mt], bf[j][0], bf[j][1]);
                    mma_f16(acc[mt][2*j+1], a[mt], bf[j][2], bf[j][3]);
                }
        }
    }

    #pragma unroll
    for (int mt = 0; mt < 2; mt++) {
        const int r0 = m0 + wm + mt * 16 + tq;
        #pragma unroll
        for (int half = 0; half < 2; half++) {
            const int m = r0 + half * 8;
            #pragma unroll
            for (int nt = 0; nt < 8; nt++) {
                const int n = n0 + wn + nt * 8 + tr * 2;
                float vx = acc[mt][nt][half * 2 + 0];
                float vy = acc[mt][nt][half * 2 + 1];
                if (mode & 1) {
                    const float2 bb = *(const float2*)(bias + n);
                    vx += bb.x; vy += bb.y;
                }
                if (mode & 2) {
                    const float2 rr = *(const float2*)(resid + (size_t)m * N + n);
                    vx += rr.x; vy += rr.y;
                }
                if (mode & 4) { vx = fmaxf(vx, 0.f); vy = fmaxf(vy, 0.f); }
                if (C16) {
                    *(__half2*)(C16 + (size_t)m * N + n) = __floats2half2_rn(vx, vy);
                } else {
                    float2 o; o.x = vx; o.y = vy;
                    *(float2*)(C + (size_t)m * N + n) = o;
                }
            }
        }
    }
}

// ---------------- Flash attention: fp16 mma, P in registers, log2-domain -----
// Q pre-scaled by 0.125*log2(e) in fp32; softmax uses bare ex2 (no mul).
#define ASH 72
#define KVBUFH (64 * ASH)
#define ATT_SMEM ((128*ASH + 2*KVBUFH + 2*KVBUFH) * 2)   // 55296 B

__global__ __launch_bounds__(256, 2)
void attn_mma_kernel(const __half* __restrict__ QKVg, __half* __restrict__ Og,
                     int ldi)
{
    extern __shared__ __half smh[];
    __half* Qs  = smh;                       // [128][72]
    __half* Ks0 = smh + 128 * ASH;           // 2 x [64][72]
    __half* Vs0 = Ks0 + 2 * KVBUFH;          // 2 x [64][72]

    const int tid  = threadIdx.x;
    const int wid  = tid >> 5, lane = tid & 31;
    const int tq   = lane >> 2, tr = lane & 3;
    const int wq0  = wid * 16;
    const int bh   = blockIdx.y;
    const int b    = bh >> 4, h = bh & 15;
    const size_t base_i = (size_t)b * SS * ldi + (size_t)h * DK;
    const size_t base_o = (size_t)b * SS * DD + (size_t)h * DK;
    const int q0   = blockIdx.x * 128;

    const __half* Qg = QKVg + base_i;
    const __half* Kg = QKVg + base_i + DD;
    const __half* Vg = QKVg + base_i + 2 * DD;

    const uint32_t sQ = smem_u32(Qs);
    const uint32_t sK = smem_u32(Ks0);
    const uint32_t sV = smem_u32(Vs0);

    const uint32_t qa = sQ + (uint32_t)((wq0 + (lane & 15)) * ASH) * 2u
                      + ((lane >> 4) << 4);
    uint32_t ka_off[4], va_off[4];
    #pragma unroll
    for (int j = 0; j < 4; j++) {
        ka_off[j] = (uint32_t)((j * 16 + (lane & 15)) * ASH) * 2u
                  + ((lane >> 4) << 4);
        va_off[j] = (uint32_t)((lane & 15) * ASH) * 2u
                  + (uint32_t)(j * 16 + ((lane >> 4) << 3)) * 2u;
    }

    // load Q tile, scale by 0.125*log2(e) in fp32, round once to fp16
    const float qsc = 0.125f * 1.4426950408889634f;
    #pragma unroll
    for (int l = 0; l < 4; l++) {
        const int idx = tid + l * 256;
        const int r = idx >> 3, c = idx & 7;
        uint4 u = *(const uint4*)(Qg + (size_t)(q0 + r) * ldi + c * 8);
        __half2* p = (__half2*)&u;
        #pragma unroll
        for (int i = 0; i < 4; i++) {
            float2 f = __half22float2(p[i]);
            p[i] = __floats2half2_rn(f.x * qsc, f.y * qsc);
        }
        *(uint4*)(Qs + r * ASH + c * 8) = u;
    }

    auto issue_kv = [&](int kt) {
        const uint32_t kb_ = sK + (uint32_t)(kt & 1) * (KVBUFH * 2u);
        const uint32_t vb_ = sV + (uint32_t)(kt & 1) * (KVBUFH * 2u);
        const int kb = kt * 64;
        #pragma unroll
        for (int l = 0; l < 2; l++) {
            const int idx = tid + l * 256;
            const int r = idx >> 3, c = idx & 7;
            cp16(kb_ + (uint32_t)(r * ASH + c * 8) * 2u,
                 Kg + (size_t)(kb + r) * ldi + c * 8);
        }
        #pragma unroll
        for (int l = 0; l < 2; l++) {
            const int idx = tid + l * 256;
            const int r = idx >> 3, c = idx & 7;
            cp16(vb_ + (uint32_t)(r * ASH + c * 8) * 2u,
                 Vg + (size_t)(kb + r) * ldi + c * 8);
        }
        asm volatile("cp.async.commit_group;" ::: "memory");
    };

    issue_kv(0);

    float m_[2], l_[2], o[8][4];
    m_[0] = m_[1] = -CUDART_INF_F;
    l_[0] = l_[1] = 0.f;
    #pragma unroll
    for (int nt = 0; nt < 8; nt++)
        #pragma unroll
        for (int i = 0; i < 4; i++) o[nt][i] = 0.f;

    const int ntiles = SS / 64;
    for (int kt = 0; kt < ntiles; kt++) {
        asm volatile("cp.async.wait_group 0;" ::: "memory");
        __syncthreads();
        if (kt + 1 < ntiles) issue_kv(kt + 1);

        const uint32_t bufb = (uint32_t)(kt & 1) * (KVBUFH * 2u);

        // S' = (Q*log2e/8) @ K^T   (log2-domain scores)
        float s[8][4];
        #pragma unroll
        for (int nt = 0; nt < 8; nt++)
            #pragma unroll
            for (int i = 0; i < 4; i++) s[nt][i] = 0.f;

        #pragma unroll
        for (int ks = 0; ks < 4; ks++) {
            const uint32_t koff = (uint32_t)ks * 32u;
            uint32_t a[4];
            ldsm4(a, qa + koff);
            #pragma unroll
            for (int j = 0; j < 4; j++) {
                uint32_t kf[4];
                ldsm4(kf, sK + bufb + ka_off[j] + koff);
                mma_f16(s[2*j],   a, kf[0], kf[2]);
                mma_f16(s[2*j+1], a, kf[1], kf[3]);
            }
        }

        // online softmax in log2 domain (rows tq, tq+8): p = 2^(s' - m')
        #pragma unroll
        for (int half = 0; half < 2; half++) {
            float mx = -CUDART_INF_F;
            #pragma unroll
            for (int nt = 0; nt < 8; nt++)
                mx = fmaxf(mx, fmaxf(s[nt][half * 2], s[nt][half * 2 + 1]));
            mx = fmaxf(mx, __shfl_xor_sync(0xffffffffu, mx, 1));
            mx = fmaxf(mx, __shfl_xor_sync(0xffffffffu, mx, 2));
            const float mn   = fmaxf(m_[half], mx);
            const float corr = ex2f(m_[half] - mn);
            m_[half] = mn;
            float sum = 0.f;
            #pragma unroll
            for (int nt = 0; nt < 8; nt++) {
                float p0 = ex2f(s[nt][half * 2]     - mn);
                float p1 = ex2f(s[nt][half * 2 + 1] - mn);
                s[nt][half * 2]     = p0;
                s[nt][half * 2 + 1] = p1;
                sum += p0 + p1;
            }
            sum += __shfl_xor_sync(0xffffffffu, sum, 1);
            sum += __shfl_xor_sync(0xffffffffu, sum, 2);
            l_[half] = l_[half] * corr + sum;
            #pragma unroll
            for (int nt = 0; nt < 8; nt++) {
                o[nt][half * 2]     *= corr;
                o[nt][half * 2 + 1] *= corr;
            }
        }

        // O += P @ V — P fragments packed directly from S accumulators
        #pragma unroll
        for (int j = 0; j < 4; j++) {
            uint32_t a[4];
            a[0] = packh2(s[2*j][0],   s[2*j][1]);
            a[1] = packh2(s[2*j][2],   s[2*j][3]);
            a[2] = packh2(s[2*j+1][0], s[2*j+1][1]);
            a[3] = packh2(s[2*j+1][2], s[2*j+1][3]);
            const uint32_t voff = bufb + (uint32_t)j * (16u * ASH * 2u);
            #pragma unroll
            for (int jj = 0; jj < 4; jj++) {
                uint32_t vf[4];
                ldsm4t(vf, sV + voff + va_off[jj]);
                mma_f16(o[2*jj],   a, vf[0], vf[1]);
                mma_f16(o[2*jj+1], a, vf[2], vf[3]);
            }
        }
    }

    const float inv0 = 1.0f / l_[0];
    const float inv1 = 1.0f / l_[1];
    #pragma unroll
    for (int nt = 0; nt < 8; nt++) {
        const int col = nt * 8 + tr * 2;
        *(__half2*)(Og + base_o + (size_t)(q0 + wq0 + tq) * DD + col) =
            __floats2half2_rn(o[nt][0] * inv0, o[nt][1] * inv0);
        *(__half2*)(Og + base_o + (size_t)(q0 + wq0 + tq + 8) * DD + col) =
            __floats2half2_rn(o[nt][2] * inv1, o[nt][3] * inv1);
    }
}

// ---------------- launch -----------------------------------------------------
extern "C" void kernel_launch(void* const* d_in, const int* in_sizes, int n_in,
                              void* d_out, int out_size)
{
    const float* X   = (const float*)d_in[0];
    const float* Wq  = (const float*)d_in[1];
    const float* Wk  = (const float*)d_in[2];
    const float* Wv  = (const float*)d_in[3];
    const float* Wo  = (const float*)d_in[4];
    const float* W1  = (const float*)d_in[5];
    const float* b1  = (const float*)d_in[6];
    const float* W2  = (const float*)d_in[7];
    const float* b2  = (const float*)d_in[8];
    const float* g1  = (const float*)d_in[9];
    const float* be1 = (const float*)d_in[10];
    const float* g2  = (const float*)d_in[11];
    const float* be2 = (const float*)d_in[12];
    float* out = (float*)d_out;

    __half *nX16, *qkv16, *ctx16, *h16, *Wqkv16, *Wo16, *W1h, *W2h;
    float *X1;
    cudaGetSymbolAddress((void**)&nX16,   g_nX16);
    cudaGetSymbolAddress((void**)&qkv16,  g_qkv16);
    cudaGetSymbolAddress((void**)&ctx16,  g_ctx16);
    cudaGetSymbolAddress((void**)&h16,    g_h16);
    cudaGetSymbolAddress((void**)&X1,     g_X1);
    cudaGetSymbolAddress((void**)&Wqkv16, g_Wqkv16);
    cudaGetSymbolAddress((void**)&Wo16,   g_Wo16);
    cudaGetSymbolAddress((void**)&W1h,    g_W1h);
    cudaGetSymbolAddress((void**)&W2h,    g_W2h);

    cudaFuncSetAttribute(tc_gemm, cudaFuncAttributeMaxDynamicSharedMemorySize,
                         TC_SMEM);
    cudaFuncSetAttribute(attn_mma_kernel,
                         cudaFuncAttributeMaxDynamicSharedMemorySize, ATT_SMEM);

    dim3 thr(256);

    // 1: single fused weight convert
    convert_all_kernel<<<2048, thr>>>(Wq, Wk, Wv, Wo, W1, W2,
                                      Wqkv16, Wo16, W1h, W2h);

    // 2: LN1
    ln_kernel<<<MR, thr>>>(X, g1, be1, nX16);

    // 3: fused QKV projection
    tc_gemm<<<dim3(QKVN/128, MR/128), thr, TC_SMEM>>>(
        nX16, Wqkv16, nullptr, qkv16, MR, QKVN, DD, nullptr, nullptr, 0);

    // 4: attention
    attn_mma_kernel<<<dim3(SS/128, BB*HH), thr, ATT_SMEM>>>(qkv16, ctx16, QKVN);

    // 5: output projection + residual -> X1 fp32
    tc_gemm<<<dim3(DD/128, MR/128), thr, TC_SMEM>>>(
        ctx16, Wo16, X1, nullptr, MR, DD, DD, nullptr, X, 2);

    // 6: LN2
    ln_kernel<<<MR, thr>>>(X1, g2, be2, nX16);

    // 7: FFN up
    tc_gemm<<<dim3(FF/128, MR/128), thr, TC_SMEM>>>(
        nX16, W1h, nullptr, h16, MR, FF, DD, b1, nullptr, 1 | 4);

    // 8: FFN down + residual
    tc_gemm<<<dim3(DD/128, MR/128), thr, TC_SMEM>>>(
        h16, W2h, out, nullptr, MR, DD, FF, b2, X1, 1 | 2);
}